// round 4
// baseline (speedup 1.0000x reference)
#include <cuda_runtime.h>
#include <cuda_bf16.h>
#include <cstdint>

// ---------------- scratch (device globals; no allocation allowed) ----------
#define MAX_N 100000
#define MAX_E 1600000
#define DF 128

__device__ float g_pooled[(size_t)MAX_N * DF];
__device__ float g_y1[(size_t)MAX_N * DF];
__device__ float g_stats[512];
__device__ float g_sf1[256];
__device__ float g_sf2[256];

// CSR scratch
__device__ int g_deg[MAX_N + 2];
__device__ int g_off[MAX_N + 2];
__device__ int g_cur[MAX_N + 2];
__device__ int g_blocksum[256];
__device__ int g_srcsorted[MAX_E];

// ==================== helpers ================================================

__device__ __forceinline__ uint32_t f32_to_tf32(float x) {
    uint32_t r;
    asm("cvt.rna.tf32.f32 %0, %1;" : "=r"(r) : "f"(x));
    return r;
}

__device__ __forceinline__ void mma_tf32(float c[4], const uint32_t a[4],
                                         uint32_t b0, uint32_t b1) {
    asm volatile(
        "mma.sync.aligned.m16n8k8.row.col.f32.tf32.tf32.f32 "
        "{%0,%1,%2,%3}, {%4,%5,%6,%7}, {%8,%9}, {%0,%1,%2,%3};"
        : "+f"(c[0]), "+f"(c[1]), "+f"(c[2]), "+f"(c[3])
        : "r"(a[0]), "r"(a[1]), "r"(a[2]), "r"(a[3]), "r"(b0), "r"(b1));
}

// ==================== small utility kernels =================================

__global__ void zero_stats_kernel() {
    int t = threadIdx.x;
    if (t < 512) g_stats[t] = 0.f;
}

__global__ void zero_deg_kernel(int total) {
    int i = blockIdx.x * blockDim.x + threadIdx.x;
    if (i < total) g_deg[i] = 0;
}

__global__ void count_kernel(const int* __restrict__ edst, int E) {
    int i = blockIdx.x * blockDim.x + threadIdx.x;
    if (i < E) atomicAdd(&g_deg[edst[i]], 1);
}

__global__ void scan_block_sums(int total) {
    __shared__ int sdata[256];
    int b = blockIdx.x;
    int base = b * 1024;
    int t = threadIdx.x;
    int s = 0;
    for (int i = t; i < 1024; i += 256) {
        int g = base + i;
        s += (g < total) ? g_deg[g] : 0;
    }
    sdata[t] = s;
    __syncthreads();
    for (int o = 128; o > 0; o >>= 1) {
        if (t < o) sdata[t] += sdata[t + o];
        __syncthreads();
    }
    if (t == 0) g_blocksum[b] = sdata[0];
}

__global__ void scan_totals(int NB) {
    int acc = 0;
    for (int i = 0; i < NB; i++) {
        int v = g_blocksum[i];
        g_blocksum[i] = acc;
        acc += v;
    }
}

__global__ void scan_final(int total) {
    __shared__ int sm[1024];
    int t = threadIdx.x;
    int g = blockIdx.x * 1024 + t;
    int x = (g < total) ? g_deg[g] : 0;
    sm[t] = x;
    __syncthreads();
#pragma unroll
    for (int o = 1; o < 1024; o <<= 1) {
        int v = (t >= o) ? sm[t - o] : 0;
        __syncthreads();
        sm[t] += v;
        __syncthreads();
    }
    int excl = g_blocksum[blockIdx.x] + sm[t] - x;
    if (g < total) {
        g_off[g] = excl;
        g_cur[g] = excl;
    }
}

__global__ void fill_kernel(const int* __restrict__ esrc,
                            const int* __restrict__ edst, int E) {
    int i = blockIdx.x * blockDim.x + threadIdx.x;
    if (i < E) {
        int d = edst[i];
        int pos = atomicAdd(&g_cur[d], 1);
        g_srcsorted[pos] = esrc[i];
    }
}

// ---------------- gather: pooled[i] = (1+eps)*h[i] + sum_{s in nbr(i)} h[s] -

__global__ void gather_kernel(const float4* __restrict__ h4,
                              const float* __restrict__ eps, int N) {
    int gwarp = (blockIdx.x * blockDim.x + threadIdx.x) >> 5;
    if (gwarp >= N) return;
    int lane = threadIdx.x & 31;
    int node = gwarp;

    float c = 1.f + eps[0];
    float4 self = __ldg(&h4[(long long)node * 32 + lane]);
    float4 acc;
    acc.x = self.x * c; acc.y = self.y * c; acc.z = self.z * c; acc.w = self.w * c;

    int begin = g_off[node];
    int end = g_off[node + 1];

    for (int j0 = begin; j0 < end; j0 += 32) {
        int cnt = min(32, end - j0);
        int myIdx = (lane < cnt) ? g_srcsorted[j0 + lane] : 0;
        int t = 0;
        for (; t + 4 <= cnt; t += 4) {
            int s0 = __shfl_sync(0xffffffff, myIdx, t + 0);
            int s1 = __shfl_sync(0xffffffff, myIdx, t + 1);
            int s2 = __shfl_sync(0xffffffff, myIdx, t + 2);
            int s3 = __shfl_sync(0xffffffff, myIdx, t + 3);
            float4 v0 = __ldg(&h4[(long long)s0 * 32 + lane]);
            float4 v1 = __ldg(&h4[(long long)s1 * 32 + lane]);
            float4 v2 = __ldg(&h4[(long long)s2 * 32 + lane]);
            float4 v3 = __ldg(&h4[(long long)s3 * 32 + lane]);
            acc.x += v0.x + v1.x; acc.y += v0.y + v1.y;
            acc.z += v0.z + v1.z; acc.w += v0.w + v1.w;
            acc.x += v2.x + v3.x; acc.y += v2.y + v3.y;
            acc.z += v2.z + v3.z; acc.w += v2.w + v3.w;
        }
        for (; t < cnt; t++) {
            int s = __shfl_sync(0xffffffff, myIdx, t);
            float4 v = __ldg(&h4[(long long)s * 32 + lane]);
            acc.x += v.x; acc.y += v.y; acc.z += v.z; acc.w += v.w;
        }
    }
    reinterpret_cast<float4*>(g_pooled)[(long long)node * 32 + lane] = acc;
}

// ==================== tensor-core GEMM (3xTF32 via mma.sync) =================
// Block: 128 threads (4 warps). Each block: 128 rows x 128 cols, K=128.
// Each warp: 32 rows (2 m16 tiles) x 128 cols (16 n8 tiles).
// D = A_hi*W_hi + A_lo*W_hi + A_hi*W_lo   (tf32 splits of fp32)
//
// SMEM: As fp32 [128][132] (padded), Whi/Wlo tf32 [128][136] (padded).

#define AS_STRIDE 132
#define W_STRIDE 136
#define AS_WORDS (128 * AS_STRIDE)
#define W_WORDS  (128 * W_STRIDE)
#define GEMM_SMEM_BYTES ((AS_WORDS + 2 * W_WORDS) * 4)

template <bool TRANSFORM>
__global__ __launch_bounds__(128)
void gemm_mma_kernel(const float* __restrict__ A,
                     const float* __restrict__ W,
                     const float* __restrict__ bias,
                     const float* __restrict__ sf,
                     float* __restrict__ Y, int M) {
    extern __shared__ float smf[];
    float* As = smf;
    uint32_t* Whi = reinterpret_cast<uint32_t*>(smf + AS_WORDS);
    uint32_t* Wlo = Whi + W_WORDS;

    int tid = threadIdx.x;
    int lane = tid & 31;
    int warp = tid >> 5;
    int g = lane >> 2;
    int t = lane & 3;
    int blockRow = blockIdx.x * 128;

    // ---- stage W: thread tid owns k-row tid
    {
        int k = tid;
        const float4* wp = reinterpret_cast<const float4*>(W + (size_t)k * 128);
        uint32_t* whp = Whi + (size_t)k * W_STRIDE;
        uint32_t* wlp = Wlo + (size_t)k * W_STRIDE;
#pragma unroll 8
        for (int c = 0; c < 32; c++) {
            float4 v = __ldg(&wp[c]);
            float vv[4] = {v.x, v.y, v.z, v.w};
            uint4 hi, lo;
            uint32_t* hip = &hi.x;
            uint32_t* lop = &lo.x;
#pragma unroll
            for (int q = 0; q < 4; q++) {
                uint32_t h = f32_to_tf32(vv[q]);
                hip[q] = h;
                lop[q] = f32_to_tf32(vv[q] - __uint_as_float(h));
            }
            *reinterpret_cast<uint4*>(whp + c * 4) = hi;
            *reinterpret_cast<uint4*>(wlp + c * 4) = lo;
        }
    }

    // ---- stage A: thread tid owns row blockRow+tid (fp32, post-transform)
    {
        int row = blockRow + tid;
        float* ap = As + (size_t)tid * AS_STRIDE;
        if (row < M) {
            const float4* gp = reinterpret_cast<const float4*>(A + (size_t)row * 128);
#pragma unroll 8
            for (int c = 0; c < 32; c++) {
                float4 v = __ldg(&gp[c]);
                if (TRANSFORM) {
                    int k = c * 4;
                    v.x = fmaxf(fmaf(v.x, __ldg(&sf[k + 0]), __ldg(&sf[128 + k + 0])), 0.f);
                    v.y = fmaxf(fmaf(v.y, __ldg(&sf[k + 1]), __ldg(&sf[128 + k + 1])), 0.f);
                    v.z = fmaxf(fmaf(v.z, __ldg(&sf[k + 2]), __ldg(&sf[128 + k + 2])), 0.f);
                    v.w = fmaxf(fmaf(v.w, __ldg(&sf[k + 3]), __ldg(&sf[128 + k + 3])), 0.f);
                }
                *reinterpret_cast<float4*>(ap + c * 4) = v;
            }
        } else {
            float4 z = {0.f, 0.f, 0.f, 0.f};
#pragma unroll 8
            for (int c = 0; c < 32; c++)
                *reinterpret_cast<float4*>(ap + c * 4) = z;
        }
    }
    __syncthreads();

    // ---- main loop
    float acc[2][16][4];
#pragma unroll
    for (int mt = 0; mt < 2; mt++)
#pragma unroll
        for (int nt = 0; nt < 16; nt++)
#pragma unroll
            for (int q = 0; q < 4; q++) acc[mt][nt][q] = 0.f;

    int rw = warp * 32;

#pragma unroll 1
    for (int ks = 0; ks < 16; ks++) {
        int k0 = ks * 8;
        uint32_t ah[2][4], al[2][4];
#pragma unroll
        for (int mt = 0; mt < 2; mt++) {
            int r = rw + mt * 16 + g;
            float x0 = As[(size_t)r * AS_STRIDE + k0 + t];
            float x1 = As[(size_t)(r + 8) * AS_STRIDE + k0 + t];
            float x2 = As[(size_t)r * AS_STRIDE + k0 + t + 4];
            float x3 = As[(size_t)(r + 8) * AS_STRIDE + k0 + t + 4];
            uint32_t h0 = f32_to_tf32(x0), h1 = f32_to_tf32(x1);
            uint32_t h2 = f32_to_tf32(x2), h3 = f32_to_tf32(x3);
            ah[mt][0] = h0; ah[mt][1] = h1; ah[mt][2] = h2; ah[mt][3] = h3;
            al[mt][0] = f32_to_tf32(x0 - __uint_as_float(h0));
            al[mt][1] = f32_to_tf32(x1 - __uint_as_float(h1));
            al[mt][2] = f32_to_tf32(x2 - __uint_as_float(h2));
            al[mt][3] = f32_to_tf32(x3 - __uint_as_float(h3));
        }

#pragma unroll
        for (int nt = 0; nt < 16; nt++) {
            int n = nt * 8 + g;
            uint32_t b0h = Whi[(size_t)(k0 + t) * W_STRIDE + n];
            uint32_t b1h = Whi[(size_t)(k0 + t + 4) * W_STRIDE + n];
            uint32_t b0l = Wlo[(size_t)(k0 + t) * W_STRIDE + n];
            uint32_t b1l = Wlo[(size_t)(k0 + t + 4) * W_STRIDE + n];
#pragma unroll
            for (int mt = 0; mt < 2; mt++) {
                mma_tf32(acc[mt][nt], ah[mt], b0h, b1h);
                mma_tf32(acc[mt][nt], al[mt], b0h, b1h);
                mma_tf32(acc[mt][nt], ah[mt], b0l, b1l);
            }
        }
    }

    // ---- epilogue: acc + bias -> Y
#pragma unroll
    for (int mt = 0; mt < 2; mt++) {
        int r0 = blockRow + rw + mt * 16 + g;
        int r1 = r0 + 8;
#pragma unroll
        for (int nt = 0; nt < 16; nt++) {
            int col = nt * 8 + 2 * t;
            float bx = __ldg(&bias[col]);
            float by = __ldg(&bias[col + 1]);
            if (r0 < M) {
                float2 v = {acc[mt][nt][0] + bx, acc[mt][nt][1] + by};
                *reinterpret_cast<float2*>(Y + (size_t)r0 * 128 + col) = v;
            }
            if (r1 < M) {
                float2 v = {acc[mt][nt][2] + bx, acc[mt][nt][3] + by};
                *reinterpret_cast<float2*>(Y + (size_t)r1 * 128 + col) = v;
            }
        }
    }
}

// ---------------- column stats: sum / sumsq over rows -----------------------

__global__ __launch_bounds__(256)
void stats_kernel(const float4* __restrict__ Y4, float* __restrict__ gsum, int M) {
    __shared__ float red[8][128];
    int tid = threadIdx.x;
    int cx = tid & 31;
    int ry = tid >> 5;
    int c0 = cx * 4;

    float s[4] = {0.f, 0.f, 0.f, 0.f};
    float q[4] = {0.f, 0.f, 0.f, 0.f};
    for (int row = blockIdx.x * 8 + ry; row < M; row += gridDim.x * 8) {
        float4 v = Y4[(long long)row * 32 + cx];
        s[0] += v.x; s[1] += v.y; s[2] += v.z; s[3] += v.w;
        q[0] += v.x * v.x; q[1] += v.y * v.y; q[2] += v.z * v.z; q[3] += v.w * v.w;
    }
#pragma unroll
    for (int j = 0; j < 4; j++) red[ry][c0 + j] = s[j];
    __syncthreads();
    if (tid < 128) {
        float t2 = 0.f;
#pragma unroll
        for (int i = 0; i < 8; i++) t2 += red[i][tid];
        atomicAdd(&gsum[tid], t2);
    }
    __syncthreads();
#pragma unroll
    for (int j = 0; j < 4; j++) red[ry][c0 + j] = q[j];
    __syncthreads();
    if (tid < 128) {
        float t2 = 0.f;
#pragma unroll
        for (int i = 0; i < 8; i++) t2 += red[i][tid];
        atomicAdd(&gsum[128 + tid], t2);
    }
}

__global__ void finalize_stats_kernel(const float* __restrict__ gsum,
                                      const float* __restrict__ gamma,
                                      const float* __restrict__ beta,
                                      float* __restrict__ sf, float invN) {
    int c = threadIdx.x;
    float mu = gsum[c] * invN;
    float var = gsum[128 + c] * invN - mu * mu;
    float rstd = rsqrtf(var + 1e-5f);
    float scale = gamma[c] * rstd;
    sf[c] = scale;
    sf[128 + c] = fmaf(-mu, scale, beta[c]);
}

__global__ void apply_bn_relu_kernel(float4* __restrict__ out,
                                     const float* __restrict__ sf, int total4) {
    int i = blockIdx.x * blockDim.x + threadIdx.x;
    if (i >= total4) return;
    int c = (i * 4) & 127;
    float4 v = out[i];
    v.x = fmaxf(fmaf(v.x, sf[c + 0], sf[128 + c + 0]), 0.f);
    v.y = fmaxf(fmaf(v.y, sf[c + 1], sf[128 + c + 1]), 0.f);
    v.z = fmaxf(fmaf(v.z, sf[c + 2], sf[128 + c + 2]), 0.f);
    v.w = fmaxf(fmaf(v.w, sf[c + 3], sf[128 + c + 3]), 0.f);
    out[i] = v;
}

// ---------------- launch -----------------------------------------------------

extern "C" void kernel_launch(void* const* d_in, const int* in_sizes, int n_in,
                              void* d_out, int out_size) {
    const float* h    = (const float*)d_in[0];
    const int*  esrc  = (const int*)d_in[1];
    const int*  edst  = (const int*)d_in[2];
    const float* W1   = (const float*)d_in[3];
    const float* b1   = (const float*)d_in[4];
    const float* g1   = (const float*)d_in[5];
    const float* be1  = (const float*)d_in[6];
    const float* W2   = (const float*)d_in[7];
    const float* b2   = (const float*)d_in[8];
    const float* g2   = (const float*)d_in[9];
    const float* be2  = (const float*)d_in[10];
    const float* eps  = (const float*)d_in[11];

    int N = in_sizes[0] / DF;
    int E = in_sizes[1];
    float* out = (float*)d_out;

    float* pooled = nullptr;
    float* y1 = nullptr;
    float* stats = nullptr;
    float* sf1 = nullptr;
    float* sf2 = nullptr;
    cudaGetSymbolAddress((void**)&pooled, g_pooled);
    cudaGetSymbolAddress((void**)&y1,     g_y1);
    cudaGetSymbolAddress((void**)&stats,  g_stats);
    cudaGetSymbolAddress((void**)&sf1,    g_sf1);
    cudaGetSymbolAddress((void**)&sf2,    g_sf2);

    cudaFuncSetAttribute(gemm_mma_kernel<false>,
                         cudaFuncAttributeMaxDynamicSharedMemorySize, GEMM_SMEM_BYTES);
    cudaFuncSetAttribute(gemm_mma_kernel<true>,
                         cudaFuncAttributeMaxDynamicSharedMemorySize, GEMM_SMEM_BYTES);

    int total4 = N * (DF / 4);
    int scanTotal = N + 1;
    int NB = (scanTotal + 1023) / 1024;

    // 0) zero accumulators
    zero_stats_kernel<<<1, 512>>>();
    zero_deg_kernel<<<(scanTotal + 255) / 256, 256>>>(scanTotal);

    // 1) CSR build
    count_kernel<<<(E + 255) / 256, 256>>>(edst, E);
    scan_block_sums<<<NB, 256>>>(scanTotal);
    scan_totals<<<1, 1>>>(NB);
    scan_final<<<NB, 1024>>>(scanTotal);
    fill_kernel<<<(E + 255) / 256, 256>>>(esrc, edst, E);

    // 2) gather-pool
    long long gthreads = (long long)N * 32;
    gather_kernel<<<(int)((gthreads + 255) / 256), 256>>>(
        (const float4*)h, eps, N);

    // 3) y1 = pooled @ W1 + b1 (mma.sync 3xTF32)
    int gblocks = (N + 127) / 128;
    gemm_mma_kernel<false><<<gblocks, 128, GEMM_SMEM_BYTES>>>(
        pooled, W1, b1, nullptr, y1, N);

    // 4) BN1 stats + finalize
    stats_kernel<<<432, 256>>>((const float4*)y1, stats, N);
    finalize_stats_kernel<<<1, 128>>>(stats, g1, be1, sf1, 1.f / (float)N);

    // 5) out = relu(bn1(y1)) @ W2 + b2 (transform fused into A load)
    gemm_mma_kernel<true><<<gblocks, 128, GEMM_SMEM_BYTES>>>(
        y1, W2, b2, sf1, out, N);

    // 6) BN2 stats + finalize
    stats_kernel<<<432, 256>>>((const float4*)out, stats + 256, N);
    finalize_stats_kernel<<<1, 128>>>(stats + 256, g2, be2, sf2, 1.f / (float)N);

    // 7) out = relu(bn2(out))
    apply_bn_relu_kernel<<<(total4 + 255) / 256, 256>>>((float4*)out, sf2, total4);
}